// round 1
// baseline (speedup 1.0000x reference)
#include <cuda_runtime.h>

// Problem constants
#define BB   8
#define HH   384
#define WW   384
#define CIN  8     // concat(pf,cf,mv) channels
#define OCH  18    // offset channels (9 taps x 2)
#define TW   32    // tile width (pixels)
#define TH   16    // tile height (pixels)
#define SW   34    // TW + 2 halo
#define SH   18    // TH + 2 halo

// ---- packed fp32x2 helpers (sm_100+ ; ptxas never auto-fuses these) ----
__device__ __forceinline__ unsigned long long pk2(float lo, float hi) {
    unsigned long long r;
    asm("mov.b64 %0, {%1, %2};" : "=l"(r) : "f"(lo), "f"(hi));
    return r;
}
__device__ __forceinline__ unsigned long long f2fma(unsigned long long a,
                                                    unsigned long long b,
                                                    unsigned long long c) {
    unsigned long long d;
    asm("fma.rn.f32x2 %0, %1, %2, %3;" : "=l"(d) : "l"(a), "l"(b), "l"(c));
    return d;
}
__device__ __forceinline__ float2 upk2(unsigned long long v) {
    float2 f;
    asm("mov.b64 {%0, %1}, %2;" : "=f"(f.x), "=f"(f.y) : "l"(v));
    return f;
}

// Bilinear sample of pf (3 channels, zero padding) + accumulate into out[3]
// via deform weights s_dw[o*27 + c*9 + k].
__device__ __forceinline__ void sample_acc(const float* __restrict__ pfb,
                                           float py, float px, int k,
                                           const float* __restrict__ s_dw,
                                           float* __restrict__ o) {
    float fy = floorf(py), fx = floorf(px);
    int y0 = (int)fy, x0 = (int)fx;
    float wy = py - fy, wx = px - fx;
    bool y0v = ((unsigned)y0 < (unsigned)HH);
    bool y1v = ((unsigned)(y0 + 1) < (unsigned)HH);
    bool x0v = ((unsigned)x0 < (unsigned)WW);
    bool x1v = ((unsigned)(x0 + 1) < (unsigned)WW);
    float w00 = (1.f - wy) * (1.f - wx);
    float w01 = (1.f - wy) * wx;
    float w10 = wy * (1.f - wx);
    float w11 = wy * wx;
    long idx00 = (long)y0 * WW + x0;
#pragma unroll
    for (int c = 0; c < 3; ++c) {
        const float* p = pfb + (long)c * HH * WW;
        float v00 = (y0v && x0v) ? __ldg(p + idx00)          : 0.f;
        float v01 = (y0v && x1v) ? __ldg(p + idx00 + 1)      : 0.f;
        float v10 = (y1v && x0v) ? __ldg(p + idx00 + WW)     : 0.f;
        float v11 = (y1v && x1v) ? __ldg(p + idx00 + WW + 1) : 0.f;
        float s = w00 * v00 + w01 * v01 + w10 * v10 + w11 * v11;
        o[0] += s_dw[0 * 27 + c * 9 + k] * s;
        o[1] += s_dw[1 * 27 + c * 9 + k] * s;
        o[2] += s_dw[2 * 27 + c * 9 + k] * s;
    }
}

__global__ __launch_bounds__(256)
void guided_cnn_fused(const float* __restrict__ pf,
                      const float* __restrict__ cf,
                      const float* __restrict__ mv,
                      const float* __restrict__ ow,   // (18,8,3,3)
                      const float* __restrict__ ob,   // (18,)
                      const float* __restrict__ dw,   // (3,3,3,3)
                      float* __restrict__ out) {
    __shared__ float s_x[CIN][SH][SW];                 // input tile + halo
    __shared__ unsigned long long s_w2[OCH * CIN * 9]; // splatted {w,w}
    __shared__ float s_dw[81];
    __shared__ float s_b[OCH];

    const int tid = threadIdx.y * 16 + threadIdx.x;   // blockDim = (16,16)
    const int b  = blockIdx.z;
    const int h0 = blockIdx.y * TH;
    const int w0 = blockIdx.x * TW;

    // ---- cooperative loads ----
    for (int i = tid; i < OCH * CIN * 9; i += 256) {
        float w = __ldg(ow + i);
        s_w2[i] = pk2(w, w);
    }
    for (int i = tid; i < 81; i += 256) s_dw[i] = __ldg(dw + i);
    if (tid < OCH) s_b[tid] = __ldg(ob + tid);

    for (int i = tid; i < CIN * SH * SW; i += 256) {
        int c  = i % SW;
        int r  = (i / SW) % SH;
        int ch = i / (SW * SH);
        int gh = h0 - 1 + r;
        int gw = w0 - 1 + c;
        float v = 0.f;
        if ((unsigned)gh < (unsigned)HH && (unsigned)gw < (unsigned)WW) {
            const float* src;
            if (ch < 3)      src = pf + (((long)b * 3 + ch)     * HH + gh) * WW + gw;
            else if (ch < 6) src = cf + (((long)b * 3 + ch - 3) * HH + gh) * WW + gw;
            else             src = mv + (((long)b * 2 + ch - 6) * HH + gh) * WW + gw;
            v = __ldg(src);
        }
        s_x[ch][r][c] = v;
    }
    __syncthreads();

    const int tx = threadIdx.x, ty = threadIdx.y;

    // ---- offset conv: 2 adjacent pixels per thread, packed f32x2 ----
    unsigned long long acc[OCH];
#pragma unroll
    for (int o = 0; o < OCH; ++o) {
        float bv = s_b[o];
        acc[o] = pk2(bv, bv);
    }

#pragma unroll
    for (int ci = 0; ci < CIN; ++ci) {
#pragma unroll
        for (int ky = 0; ky < 3; ++ky) {
            const float* rp = &s_x[ci][ty + ky][2 * tx];
            float2 ab = *reinterpret_cast<const float2*>(rp);       // v0,v1
            float2 cd = *reinterpret_cast<const float2*>(rp + 2);   // v2,v3
            unsigned long long p0 = pk2(ab.x, ab.y);  // kx=0: pixels {0,1}
            unsigned long long p1 = pk2(ab.y, cd.x);  // kx=1
            unsigned long long p2 = pk2(cd.x, cd.y);  // kx=2
            const unsigned long long* wb = &s_w2[ci * 9 + ky * 3];
#pragma unroll
            for (int o = 0; o < OCH; ++o) {
                acc[o] = f2fma(p0, wb[o * 72 + 0], acc[o]);
                acc[o] = f2fma(p1, wb[o * 72 + 1], acc[o]);
                acc[o] = f2fma(p2, wb[o * 72 + 2], acc[o]);
            }
        }
    }

    // ---- deformable sampling + 3x3x9 einsum ----
    const int h   = h0 + ty;
    const int wpx = w0 + 2 * tx;
    const float* pfb = pf + (long)b * 3 * HH * WW;

    float o0[3] = {0.f, 0.f, 0.f};
    float o1[3] = {0.f, 0.f, 0.f};

#pragma unroll
    for (int k = 0; k < 9; ++k) {
        const int kyi = k / 3, kxi = k % 3;
        float2 oy = upk2(acc[2 * k]);       // y-offset, lanes = pixel0/pixel1
        float2 ox = upk2(acc[2 * k + 1]);   // x-offset
        float by = (float)(kyi + h - 1);
        float bx0 = (float)(kxi + wpx - 1);
        sample_acc(pfb, oy.x + by, ox.x + bx0,       k, s_dw, o0);
        sample_acc(pfb, oy.y + by, ox.y + bx0 + 1.f, k, s_dw, o1);
    }

#pragma unroll
    for (int o = 0; o < 3; ++o) {
        float2 v = make_float2(o0[o], o1[o]);
        *reinterpret_cast<float2*>(out + (((long)b * 3 + o) * HH + h) * WW + wpx) = v;
    }
}

extern "C" void kernel_launch(void* const* d_in, const int* in_sizes, int n_in,
                              void* d_out, int out_size) {
    const float* pf = (const float*)d_in[0];
    const float* cf = (const float*)d_in[1];
    const float* mv = (const float*)d_in[2];
    const float* ow = (const float*)d_in[3];
    const float* ob = (const float*)d_in[4];
    const float* dw = (const float*)d_in[5];
    float* out = (float*)d_out;

    dim3 blk(16, 16);
    dim3 grd(WW / TW, HH / TH, BB);   // 12 x 24 x 8
    guided_cnn_fused<<<grd, blk>>>(pf, cf, mv, ow, ob, dw, out);
}

// round 2
// speedup vs baseline: 1.0114x; 1.0114x over previous
#include <cuda_runtime.h>

#define BB   8
#define HH   384
#define WW   384
#define CIN  8
#define OCH  18
#define TW   32     // tile width  (8 threads x * 4 px)
#define TH   32     // tile height (32 threads y)
#define SW   36     // padded smem row: 34 used + 2 pad (16B alignment)
#define SH   34

typedef unsigned long long ull;

__device__ __forceinline__ ull pk2(float lo, float hi) {
    ull r; asm("mov.b64 %0, {%1, %2};" : "=l"(r) : "f"(lo), "f"(hi)); return r;
}
__device__ __forceinline__ ull f2fma(ull a, ull b, ull c) {
    ull d; asm("fma.rn.f32x2 %0, %1, %2, %3;" : "=l"(d) : "l"(a), "l"(b), "l"(c)); return d;
}
__device__ __forceinline__ float2 upk2(ull v) {
    float2 f; asm("mov.b64 {%0, %1}, %2;" : "=f"(f.x), "=f"(f.y) : "l"(v)); return f;
}

// ---- dynamic smem layout (bytes) ----
#define OFF_X    0
#define SZ_X     (CIN * SH * SW * 4)          // 39168
#define OFF_W2   (OFF_X + SZ_X)               // 39168 (16B aligned)
#define SZ_W2    (CIN * 9 * OCH * 8)          // 10368
#define OFF_DW   (OFF_W2 + SZ_W2)             // 49536 (16B aligned)
#define SZ_DW    (27 * 16)                    // 432
#define OFF_B    (OFF_DW + SZ_DW)             // 49968
#define SZ_B     (OCH * 4)
#define SMEM_TOTAL (OFF_B + SZ_B)             // 50040

// Bilinear sample (3 channels, zero pad) + accumulate via float4 deform weights.
__device__ __forceinline__ void sample_px(const float* __restrict__ pfb,
                                          float py, float px,
                                          const float4* __restrict__ dwk, // &s_dw4[k], stride 9
                                          float& a0, float& a1, float& a2) {
    int y0 = __float2int_rd(py);
    int x0 = __float2int_rd(px);
    float wy = py - (float)y0;
    float wx = px - (float)x0;
    bool y0v = ((unsigned)y0 < (unsigned)HH);
    bool y1v = ((unsigned)(y0 + 1) < (unsigned)HH);
    bool x0v = ((unsigned)x0 < (unsigned)WW);
    bool x1v = ((unsigned)(x0 + 1) < (unsigned)WW);
    float iy = 1.f - wy, ix = 1.f - wx;
    float w00 = iy * ix, w01 = iy * wx, w10 = wy * ix, w11 = wy * wx;
    long i00 = (long)y0 * WW + x0;
#pragma unroll
    for (int c = 0; c < 3; ++c) {
        const float* p = pfb + (long)c * (HH * WW);
        float v00 = (y0v && x0v) ? __ldg(p + i00)          : 0.f;
        float v01 = (y0v && x1v) ? __ldg(p + i00 + 1)      : 0.f;
        float v10 = (y1v && x0v) ? __ldg(p + i00 + WW)     : 0.f;
        float v11 = (y1v && x1v) ? __ldg(p + i00 + WW + 1) : 0.f;
        float s = fmaf(w00, v00, fmaf(w01, v01, fmaf(w10, v10, w11 * v11)));
        float4 dw = dwk[c * 9];
        a0 = fmaf(dw.x, s, a0);
        a1 = fmaf(dw.y, s, a1);
        a2 = fmaf(dw.z, s, a2);
    }
}

__global__ __launch_bounds__(256, 2)
void guided_cnn_fused(const float* __restrict__ pf,
                      const float* __restrict__ cf,
                      const float* __restrict__ mv,
                      const float* __restrict__ ow,   // (18,8,3,3)
                      const float* __restrict__ ob,   // (18,)
                      const float* __restrict__ dw,   // (3,3,3,3)
                      float* __restrict__ out) {
    extern __shared__ char smem[];
    float* s_x  = (float*)(smem + OFF_X);       // [CIN][SH][SW]
    ull*   s_w2 = (ull*)  (smem + OFF_W2);      // [(ci*3+ky)*3+kx][o]  splatted {w,w}
    float4* s_dw4 = (float4*)(smem + OFF_DW);   // [c*9+k] = {dw0,dw1,dw2,-}
    float* s_b  = (float*)(smem + OFF_B);

    const int tx = threadIdx.x;                 // 0..7
    const int ty = threadIdx.y;                 // 0..31
    const int tid = ty * 8 + tx;
    const int b  = blockIdx.z;
    const int h0 = blockIdx.y * TH;
    const int w0 = blockIdx.x * TW;

    // ---- stage weights: s_w2[((ci*3+ky)*3+kx)*18 + o] = {w,w} ----
    for (int i = tid; i < CIN * 9 * OCH; i += 256) {
        int o = i % OCH;
        int t = i / OCH;
        int kx = t % 3; t /= 3;
        int ky = t % 3;
        int ci = t / 3;
        float w = __ldg(ow + ((o * CIN + ci) * 3 + ky) * 3 + kx);
        s_w2[i] = pk2(w, w);
    }
    // deform weights as float4 per (c,k)
    for (int i = tid; i < 27; i += 256) {
        int c = i / 9, k = i % 9;
        s_dw4[i] = make_float4(__ldg(dw + 0 * 27 + c * 9 + k),
                               __ldg(dw + 1 * 27 + c * 9 + k),
                               __ldg(dw + 2 * 27 + c * 9 + k), 0.f);
    }
    if (tid < OCH) s_b[tid] = __ldg(ob + tid);

    // ---- stage input tile (8 ch, halo 1) ----
    for (int i = tid; i < CIN * SH * SW; i += 256) {
        int c  = i % SW;
        int r  = (i / SW) % SH;
        int ch = i / (SW * SH);
        int gh = h0 - 1 + r;
        int gw = w0 - 1 + c;
        float v = 0.f;
        if ((unsigned)gh < (unsigned)HH && (unsigned)gw < (unsigned)WW) {
            const float* src;
            if (ch < 3)      src = pf + (((long)b * 3 + ch)     * HH + gh) * WW + gw;
            else if (ch < 6) src = cf + (((long)b * 3 + ch - 3) * HH + gh) * WW + gw;
            else             src = mv + (((long)b * 2 + ch - 6) * HH + gh) * WW + gw;
            v = __ldg(src);
        }
        s_x[i] = v;
    }
    __syncthreads();

    // ---- offset conv: 4 adjacent pixels per thread (two f32x2 pairs) ----
    ull accA[OCH], accB[OCH];
#pragma unroll
    for (int o = 0; o < OCH; ++o) {
        float bv = s_b[o];
        accA[o] = pk2(bv, bv);
        accB[o] = accA[o];
    }

#pragma unroll
    for (int ci = 0; ci < CIN; ++ci) {
#pragma unroll
        for (int ky = 0; ky < 3; ++ky) {
            const float* rp = s_x + (ci * SH + (ty + ky)) * SW + 4 * tx;
            float4 q  = *reinterpret_cast<const float4*>(rp);       // v0..v3 (16B aligned)
            float2 r2 = *reinterpret_cast<const float2*>(rp + 4);   // v4,v5
            ull u01 = pk2(q.x, q.y);
            ull u23 = pk2(q.z, q.w);
            ull u45 = pk2(r2.x, r2.y);
            ull u12 = pk2(q.y, q.z);
            ull u34 = pk2(q.w, r2.x);
            const ulonglong2* wb =
                reinterpret_cast<const ulonglong2*>(s_w2 + (ci * 3 + ky) * 3 * OCH);
#pragma unroll
            for (int o2 = 0; o2 < 9; ++o2) {
                ulonglong2 wk0 = wb[o2];          // kx=0, ch o, o+1
                ulonglong2 wk1 = wb[9 + o2];      // kx=1
                ulonglong2 wk2 = wb[18 + o2];     // kx=2
                const int o = 2 * o2;
                accA[o]   = f2fma(u01, wk0.x, accA[o]);
                accB[o]   = f2fma(u23, wk0.x, accB[o]);
                accA[o+1] = f2fma(u01, wk0.y, accA[o+1]);
                accB[o+1] = f2fma(u23, wk0.y, accB[o+1]);
                accA[o]   = f2fma(u12, wk1.x, accA[o]);
                accB[o]   = f2fma(u34, wk1.x, accB[o]);
                accA[o+1] = f2fma(u12, wk1.y, accA[o+1]);
                accB[o+1] = f2fma(u34, wk1.y, accB[o+1]);
                accA[o]   = f2fma(u23, wk2.x, accA[o]);
                accB[o]   = f2fma(u45, wk2.x, accB[o]);
                accA[o+1] = f2fma(u23, wk2.y, accA[o+1]);
                accB[o+1] = f2fma(u45, wk2.y, accB[o+1]);
            }
        }
    }

    // ---- deformable sampling + einsum, 4 pixels ----
    const int h    = h0 + ty;
    const int wpx  = w0 + 4 * tx;
    const float* pfb = pf + (long)b * 3 * HH * WW;

    float a0[4] = {0,0,0,0};   // out ch 0, pixels 0..3
    float a1[4] = {0,0,0,0};
    float a2[4] = {0,0,0,0};

#pragma unroll
    for (int k = 0; k < 9; ++k) {
        const int kyi = k / 3, kxi = k % 3;
        float2 oyA = upk2(accA[2 * k]);
        float2 oxA = upk2(accA[2 * k + 1]);
        float2 oyB = upk2(accB[2 * k]);
        float2 oxB = upk2(accB[2 * k + 1]);
        const float by  = (float)(kyi + h - 1);
        const float bx  = (float)(kxi + wpx - 1);
        const float4* dwk = s_dw4 + k;
        sample_px(pfb, oyA.x + by, oxA.x + bx,       dwk, a0[0], a1[0], a2[0]);
        sample_px(pfb, oyA.y + by, oxA.y + bx + 1.f, dwk, a0[1], a1[1], a2[1]);
        sample_px(pfb, oyB.x + by, oxB.x + bx + 2.f, dwk, a0[2], a1[2], a2[2]);
        sample_px(pfb, oyB.y + by, oxB.y + bx + 3.f, dwk, a0[3], a1[3], a2[3]);
    }

    float* ob0 = out + (((long)b * 3 + 0) * HH + h) * WW + wpx;
    float* ob1 = out + (((long)b * 3 + 1) * HH + h) * WW + wpx;
    float* ob2 = out + (((long)b * 3 + 2) * HH + h) * WW + wpx;
    *reinterpret_cast<float4*>(ob0) = make_float4(a0[0], a0[1], a0[2], a0[3]);
    *reinterpret_cast<float4*>(ob1) = make_float4(a1[0], a1[1], a1[2], a1[3]);
    *reinterpret_cast<float4*>(ob2) = make_float4(a2[0], a2[1], a2[2], a2[3]);
}

extern "C" void kernel_launch(void* const* d_in, const int* in_sizes, int n_in,
                              void* d_out, int out_size) {
    const float* pf = (const float*)d_in[0];
    const float* cf = (const float*)d_in[1];
    const float* mv = (const float*)d_in[2];
    const float* ow = (const float*)d_in[3];
    const float* ob = (const float*)d_in[4];
    const float* dw = (const float*)d_in[5];
    float* out = (float*)d_out;

    cudaFuncSetAttribute(guided_cnn_fused,
                         cudaFuncAttributeMaxDynamicSharedMemorySize, SMEM_TOTAL);

    dim3 blk(8, 32);
    dim3 grd(WW / TW, HH / TH, BB);   // 12 x 12 x 8 = 1152
    guided_cnn_fused<<<grd, blk, SMEM_TOTAL>>>(pf, cf, mv, ow, ob, dw, out);
}